// round 2
// baseline (speedup 1.0000x reference)
#include <cuda_runtime.h>
#include <cuda_fp16.h>

// V=100000, K=32, F=64.
// out[v, 0:64]   = mean over K neighbours of x[idxs[v,k], :]
// out[v, 64:128] = max  over K neighbours
//
// Two-kernel pipeline:
//  1) convert x (fp32, 25.6MB) -> fp16 scratch (12.8MB, __device__ global)
//  2) gather in fp16: each neighbour row is 128B = ONE cache line.
//     One warp per vertex, one __half2 per lane per row (4B x 32 lanes = 128B,
//     fully coalesced). Accumulate mean/max in fp32 registers.
//
// Halves the L1/L2 gather traffic that bounds the fp32 version.

#define KNN  32
#define FDIM 64
#define VMAX 100000

__device__ __half2 g_xh[VMAX * (FDIM / 2)];   // 12.8 MB scratch

__global__ __launch_bounds__(256)
void convert_kernel(const float2* __restrict__ x2, int n)  // n = V*F/2
{
    int i = blockIdx.x * blockDim.x + threadIdx.x;
    if (i < n) {
        float2 v = x2[i];
        g_xh[i] = __floats2half2_rn(v.x, v.y);
    }
}

__global__ __launch_bounds__(256)
void knn_mean_max_fp16_kernel(const int* __restrict__ idxs,
                              float2*    __restrict__ out2,
                              int V)
{
    const int warp = (blockIdx.x * blockDim.x + threadIdx.x) >> 5;
    const int lane = threadIdx.x & 31;
    if (warp >= V) return;

    // Coalesced index load: lane l holds idxs[warp][l]
    const int my_idx = idxs[warp * KNN + lane];

    float2 s = make_float2(0.0f, 0.0f);
    float2 m = make_float2(-3.402823466e+38f, -3.402823466e+38f);

    const __half2* __restrict__ xh = g_xh;

    #pragma unroll
    for (int k = 0; k < KNN; ++k) {
        const int idx = __shfl_sync(0xffffffffu, my_idx, k);
        const __half2 h = __ldg(&xh[idx * (FDIM / 2) + lane]);
        const float2 v = __half22float2(h);
        s.x += v.x;  s.y += v.y;
        m.x = fmaxf(m.x, v.x);
        m.y = fmaxf(m.y, v.y);
    }

    s.x *= (1.0f / KNN);
    s.y *= (1.0f / KNN);

    // Output row = 128 floats = 64 float2: [mean(32 float2) | max(32 float2)]
    out2[warp * FDIM + lane]      = s;
    out2[warp * FDIM + 32 + lane] = m;
}

extern "C" void kernel_launch(void* const* d_in, const int* in_sizes, int n_in,
                              void* d_out, int out_size)
{
    const float2* x2   = (const float2*)d_in[0];  // x: [V, 64] float32
    const int*    idxs = (const int*)d_in[1];     // idxs: [V, 32] int32
    float2*       out2 = (float2*)d_out;          // out: [V, 128] float32

    const int V = in_sizes[0] / FDIM;             // 100000
    const int nconv = in_sizes[0] / 2;            // V*F/2 half2 elements

    convert_kernel<<<(nconv + 255) / 256, 256>>>(x2, nconv);

    const int warps_per_block = 256 / 32;         // 8
    const int blocks = (V + warps_per_block - 1) / warps_per_block;
    knn_mean_max_fp16_kernel<<<blocks, 256>>>(idxs, out2, V);
}

// round 3
// speedup vs baseline: 1.3223x; 1.3223x over previous
#include <cuda_runtime.h>
#include <cuda_fp16.h>

// V=100000, K=32, F=64.
// out[v, 0:64]   = mean over K neighbours of x[idxs[v,k], :]
// out[v, 64:128] = max  over K neighbours
//
// Kernel 1: convert x fp32 -> fp16 scratch (row = 128B = one cache line).
// Kernel 2: warp per vertex; 8 lanes per gathered row (int4 = 8 fp16 per
//   lane), so one LDG.128 gathers 4 neighbour rows. Packed HADD2/HMAX2
//   accumulation, 2-step xor-butterfly to combine the 4 row-groups.
//   ~2x fewer instructions than the per-half2 version (issue-bound before).

#define KNN  32
#define FDIM 64
#define VMAX 100000

__device__ __align__(16) __half2 g_xh[VMAX * (FDIM / 2)];   // 12.8 MB

__global__ __launch_bounds__(256)
void convert_kernel(const float4* __restrict__ x4, int n4)   // n4 = V*F/4
{
    int i = blockIdx.x * blockDim.x + threadIdx.x;
    if (i < n4) {
        float4 v = x4[i];
        __half2 h0 = __floats2half2_rn(v.x, v.y);
        __half2 h1 = __floats2half2_rn(v.z, v.w);
        uint2 packed;
        packed.x = *(const unsigned int*)&h0;
        packed.y = *(const unsigned int*)&h1;
        *reinterpret_cast<uint2*>(&g_xh[2 * i]) = packed;
    }
}

__device__ __forceinline__ __half2 h2_shfl_xor(__half2 v, int off)
{
    unsigned int u = *(const unsigned int*)&v;
    u = __shfl_xor_sync(0xffffffffu, u, off);
    return *(const __half2*)&u;
}

__global__ __launch_bounds__(256)
void knn_mean_max_kernel(const int* __restrict__ idxs,
                         float4*    __restrict__ out4,
                         int V)
{
    const int warp = (blockIdx.x * blockDim.x + threadIdx.x) >> 5;
    const int lane = threadIdx.x & 31;
    if (warp >= V) return;

    const int g = lane >> 3;   // which of 4 rows this lane helps gather
    const int p = lane & 7;    // 16B-chunk position within the 128B row

    // Coalesced index load: lane l holds idxs[warp][l]
    const int my_idx = idxs[warp * KNN + lane];

    const __half2 zero = __float2half2_rn(0.0f);
    const __half2 ninf = __float2half2_rn(-65504.0f);
    __half2 s0 = zero, s1 = zero, s2 = zero, s3 = zero;
    __half2 m0 = ninf, m1 = ninf, m2 = ninf, m3 = ninf;

    const int4* __restrict__ xh4 = (const int4*)g_xh;   // row = 8 int4

    #pragma unroll
    for (int it = 0; it < 8; ++it) {
        const int idx = __shfl_sync(0xffffffffu, my_idx, it * 4 + g);
        const int4 d = __ldg(&xh4[idx * 8 + p]);
        const __half2 a0 = *(const __half2*)&d.x;
        const __half2 a1 = *(const __half2*)&d.y;
        const __half2 a2 = *(const __half2*)&d.z;
        const __half2 a3 = *(const __half2*)&d.w;
        s0 = __hadd2(s0, a0);  m0 = __hmax2(m0, a0);
        s1 = __hadd2(s1, a1);  m1 = __hmax2(m1, a1);
        s2 = __hadd2(s2, a2);  m2 = __hmax2(m2, a2);
        s3 = __hadd2(s3, a3);  m3 = __hmax2(m3, a3);
    }

    // Combine the 4 row-groups: lanes {p, p+8, p+16, p+24} hold same features.
    #pragma unroll
    for (int off = 8; off <= 16; off <<= 1) {
        s0 = __hadd2(s0, h2_shfl_xor(s0, off));
        s1 = __hadd2(s1, h2_shfl_xor(s1, off));
        s2 = __hadd2(s2, h2_shfl_xor(s2, off));
        s3 = __hadd2(s3, h2_shfl_xor(s3, off));
        m0 = __hmax2(m0, h2_shfl_xor(m0, off));
        m1 = __hmax2(m1, h2_shfl_xor(m1, off));
        m2 = __hmax2(m2, h2_shfl_xor(m2, off));
        m3 = __hmax2(m3, h2_shfl_xor(m3, off));
    }

    // Output row = 128 floats = 32 float4: [mean 16 float4 | max 16 float4].
    // Lane p holds features [8p, 8p+8). Lanes 0-7 write mean, 8-15 write max.
    const float inv = 1.0f / KNN;
    if (lane < 8) {
        float2 f0 = __half22float2(s0), f1 = __half22float2(s1);
        float2 f2 = __half22float2(s2), f3 = __half22float2(s3);
        float4 lo = make_float4(f0.x * inv, f0.y * inv, f1.x * inv, f1.y * inv);
        float4 hi = make_float4(f2.x * inv, f2.y * inv, f3.x * inv, f3.y * inv);
        out4[warp * 32 + 2 * p]     = lo;
        out4[warp * 32 + 2 * p + 1] = hi;
    } else if (lane < 16) {
        float2 f0 = __half22float2(m0), f1 = __half22float2(m1);
        float2 f2 = __half22float2(m2), f3 = __half22float2(m3);
        float4 lo = make_float4(f0.x, f0.y, f1.x, f1.y);
        float4 hi = make_float4(f2.x, f2.y, f3.x, f3.y);
        out4[warp * 32 + 16 + 2 * p]     = lo;
        out4[warp * 32 + 16 + 2 * p + 1] = hi;
    }
}

extern "C" void kernel_launch(void* const* d_in, const int* in_sizes, int n_in,
                              void* d_out, int out_size)
{
    const float4* x4   = (const float4*)d_in[0];  // x: [V, 64] float32
    const int*    idxs = (const int*)d_in[1];     // idxs: [V, 32] int32
    float4*       out4 = (float4*)d_out;          // out: [V, 128] float32

    const int V  = in_sizes[0] / FDIM;            // 100000
    const int n4 = in_sizes[0] / 4;               // V*F/4 float4 elements

    convert_kernel<<<(n4 + 255) / 256, 256>>>(x4, n4);

    const int warps_per_block = 256 / 32;         // 8
    const int blocks = (V + warps_per_block - 1) / warps_per_block;
    knn_mean_max_kernel<<<blocks, 256>>>(idxs, out4, V);
}

// round 4
// speedup vs baseline: 1.3245x; 1.0016x over previous
#include <cuda_runtime.h>
#include <cuda_fp16.h>

// V=100000, K=32, F=64.
// out[v, 0:64]   = mean over K neighbours of x[idxs[v,k], :]
// out[v, 64:128] = max  over K neighbours
//
// Kernel 1: convert x fp32 -> fp16 scratch (row = 128B = one cache line).
// Kernel 2: warp per vertex; 8 lanes per gathered row (int4 = 8 fp16 per
//   lane), one LDG.128 gathers 4 neighbour rows. Gather loads are issued in
//   explicit batches of 4 (separate registers) so ptxas keeps MLP=4 in
//   flight -- R3 showed regs=32 capped MLP at ~2 and left issue at 51%.
//   Packed HADD2/HMAX2 accumulation, 2-step xor-butterfly.

#define KNN  32
#define FDIM 64
#define VMAX 100000

__device__ __align__(16) __half2 g_xh[VMAX * (FDIM / 2)];   // 12.8 MB

__global__ __launch_bounds__(256)
void convert_kernel(const float4* __restrict__ x4, int n8)   // n8 = V*F/8
{
    int i = blockIdx.x * blockDim.x + threadIdx.x;
    if (i < n8) {
        float4 a = x4[2 * i];
        float4 b = x4[2 * i + 1];
        __half2 h0 = __floats2half2_rn(a.x, a.y);
        __half2 h1 = __floats2half2_rn(a.z, a.w);
        __half2 h2 = __floats2half2_rn(b.x, b.y);
        __half2 h3 = __floats2half2_rn(b.z, b.w);
        int4 packed;
        packed.x = *(const int*)&h0;
        packed.y = *(const int*)&h1;
        packed.z = *(const int*)&h2;
        packed.w = *(const int*)&h3;
        *reinterpret_cast<int4*>(&g_xh[4 * i]) = packed;
    }
}

__device__ __forceinline__ __half2 h2_shfl_xor(__half2 v, int off)
{
    unsigned int u = *(const unsigned int*)&v;
    u = __shfl_xor_sync(0xffffffffu, u, off);
    return *(const __half2*)&u;
}

__global__ __launch_bounds__(256)
void knn_mean_max_kernel(const int* __restrict__ idxs,
                         float4*    __restrict__ out4,
                         int V)
{
    const int warp = (blockIdx.x * blockDim.x + threadIdx.x) >> 5;
    const int lane = threadIdx.x & 31;
    if (warp >= V) return;

    const int g = lane >> 3;   // which of 4 rows this lane helps gather
    const int p = lane & 7;    // 16B-chunk position within the 128B row

    // Coalesced index load: lane l holds idxs[warp][l]
    const int my_idx = idxs[warp * KNN + lane];

    const __half2 zero = __float2half2_rn(0.0f);
    const __half2 ninf = __float2half2_rn(-65504.0f);
    __half2 s0 = zero, s1 = zero, s2 = zero, s3 = zero;
    __half2 m0 = ninf, m1 = ninf, m2 = ninf, m3 = ninf;

    const int4* __restrict__ xh4 = (const int4*)g_xh;   // row = 8 int4

    #pragma unroll
    for (int half = 0; half < 2; ++half) {
        // ---- batch of 4 independent gathers: keep MLP=4 in flight ----
        const int i0 = __shfl_sync(0xffffffffu, my_idx, half * 16 + 0 + g);
        const int i1 = __shfl_sync(0xffffffffu, my_idx, half * 16 + 4 + g);
        const int i2 = __shfl_sync(0xffffffffu, my_idx, half * 16 + 8 + g);
        const int i3 = __shfl_sync(0xffffffffu, my_idx, half * 16 + 12 + g);
        const int4 d0 = __ldg(&xh4[i0 * 8 + p]);
        const int4 d1 = __ldg(&xh4[i1 * 8 + p]);
        const int4 d2 = __ldg(&xh4[i2 * 8 + p]);
        const int4 d3 = __ldg(&xh4[i3 * 8 + p]);

        #pragma unroll
        for (int j = 0; j < 4; ++j) {
            const int4 d = (j == 0) ? d0 : (j == 1) ? d1 : (j == 2) ? d2 : d3;
            const __half2 a0 = *(const __half2*)&d.x;
            const __half2 a1 = *(const __half2*)&d.y;
            const __half2 a2 = *(const __half2*)&d.z;
            const __half2 a3 = *(const __half2*)&d.w;
            s0 = __hadd2(s0, a0);  m0 = __hmax2(m0, a0);
            s1 = __hadd2(s1, a1);  m1 = __hmax2(m1, a1);
            s2 = __hadd2(s2, a2);  m2 = __hmax2(m2, a2);
            s3 = __hadd2(s3, a3);  m3 = __hmax2(m3, a3);
        }
    }

    // Combine the 4 row-groups: lanes {p, p+8, p+16, p+24} hold same features.
    #pragma unroll
    for (int off = 8; off <= 16; off <<= 1) {
        s0 = __hadd2(s0, h2_shfl_xor(s0, off));
        s1 = __hadd2(s1, h2_shfl_xor(s1, off));
        s2 = __hadd2(s2, h2_shfl_xor(s2, off));
        s3 = __hadd2(s3, h2_shfl_xor(s3, off));
        m0 = __hmax2(m0, h2_shfl_xor(m0, off));
        m1 = __hmax2(m1, h2_shfl_xor(m1, off));
        m2 = __hmax2(m2, h2_shfl_xor(m2, off));
        m3 = __hmax2(m3, h2_shfl_xor(m3, off));
    }

    // Output row = 128 floats = 32 float4: [mean 16 float4 | max 16 float4].
    // Lane p holds features [8p, 8p+8). Lanes 0-7 write mean, 8-15 write max.
    const float inv = 1.0f / KNN;
    if (lane < 8) {
        float2 f0 = __half22float2(s0), f1 = __half22float2(s1);
        float2 f2 = __half22float2(s2), f3 = __half22float2(s3);
        float4 lo = make_float4(f0.x * inv, f0.y * inv, f1.x * inv, f1.y * inv);
        float4 hi = make_float4(f2.x * inv, f2.y * inv, f3.x * inv, f3.y * inv);
        out4[warp * 32 + 2 * p]     = lo;
        out4[warp * 32 + 2 * p + 1] = hi;
    } else if (lane < 16) {
        float2 f0 = __half22float2(m0), f1 = __half22float2(m1);
        float2 f2 = __half22float2(m2), f3 = __half22float2(m3);
        float4 lo = make_float4(f0.x, f0.y, f1.x, f1.y);
        float4 hi = make_float4(f2.x, f2.y, f3.x, f3.y);
        out4[warp * 32 + 16 + 2 * p]     = lo;
        out4[warp * 32 + 16 + 2 * p + 1] = hi;
    }
}

extern "C" void kernel_launch(void* const* d_in, const int* in_sizes, int n_in,
                              void* d_out, int out_size)
{
    const float4* x4   = (const float4*)d_in[0];  // x: [V, 64] float32
    const int*    idxs = (const int*)d_in[1];     // idxs: [V, 32] int32
    float4*       out4 = (float4*)d_out;          // out: [V, 128] float32

    const int V  = in_sizes[0] / FDIM;            // 100000
    const int n8 = in_sizes[0] / 8;               // V*F/8 (16B per thread)

    convert_kernel<<<(n8 + 255) / 256, 256>>>(x4, n8);

    const int warps_per_block = 256 / 32;         // 8
    const int blocks = (V + warps_per_block - 1) / warps_per_block;
    knn_mean_max_kernel<<<blocks, 256>>>(idxs, out4, V);
}